// round 4
// baseline (speedup 1.0000x reference)
#include <cuda_runtime.h>
#include <math_constants.h>

#define W      8192
#define ROWS   4096      // 16 * 1 * 256
#define NLAG   4096      // W / 2
#define TPB    512
#define EPT    16        // elements per thread (TPB * EPT == W)
#define NWARP  (TPB / 32)
#define GRID   592       // 148 SMs * 4 blocks/SM, persistent
#define CAP    128       // candidate buffer capacity (expected ~3-8 used)

__device__ __forceinline__ bool better(float v, int i, float v2, int i2) {
    return (v > v2) || (v == v2 && i < i2);
}

__device__ __forceinline__ void ins3(float v, int i,
                                     float& s0, int& i0,
                                     float& s1, int& i1,
                                     float& s2, int& i2) {
    if (better(v, i, s0, i0)) {
        s2 = s1; i2 = i1;
        s1 = s0; i1 = i0;
        s0 = v;  i0 = i;
    } else if (better(v, i, s1, i1)) {
        s2 = s1; i2 = i1;
        s1 = v;  i1 = i;
    } else if (better(v, i, s2, i2)) {
        s2 = v;  i2 = i;
    }
}

// Merge sorted (desc) triple (b0,b1,b2) into (a0,a1,a2). Values only, FMNMX net.
__device__ __forceinline__ void merge3(float& a0, float& a1, float& a2,
                                       float b0, float b1, float b2) {
    float r0 = fmaxf(a0, b0);
    float x  = fminf(a0, b0);
    float y  = fmaxf(a1, b1);
    float z  = fminf(a1, b1);
    float r1 = fmaxf(x, y);
    float s  = fminf(x, y);
    float r2 = fmaxf(fmaxf(s, z), fmaxf(a2, b2));
    a0 = r0; a1 = r1; a2 = r2;
}

__global__ __launch_bounds__(TPB, 4)
void peaks_kernel(const float* __restrict__ x, float* __restrict__ out) {
    const int t   = threadIdx.x;
    const int lid = t & 31;
    const int wid = t >> 5;
    const int start = t * EPT;
    const unsigned fm = 0xffffffffu;

    __shared__ float s_wtop[NWARP][3];
    __shared__ int   s_cnt;
    __shared__ float s_val[CAP];
    __shared__ int   s_idx[CAP];

    if (t == 0) s_cnt = 0;   // first-iteration init (B1 below orders it)

    for (int row = blockIdx.x; row < ROWS; row += GRID) {
        const float* __restrict__ xr = x + (size_t)row * W;

        // ---- Load chunk (4x LDG.128, front-batched) ----
        float c[EPT];
        const float4* p = reinterpret_cast<const float4*>(xr + start);
#pragma unroll
        for (int q = 0; q < EPT / 4; q++) {
            float4 v = p[q];
            c[q * 4 + 0] = v.x;
            c[q * 4 + 1] = v.y;
            c[q * 4 + 2] = v.z;
            c[q * 4 + 3] = v.w;
        }

        // ---- Cross-warp halo: 2 predicated scalar loads per warp ----
        float pl = -CUDART_INF_F, pn = -CUDART_INF_F;
        if (lid == 0 && t > 0)             pl = __ldg(xr + start - 1);
        if (lid == 31 && t < TPB - 1)      pn = __ldg(xr + start + EPT);

        // ---- Intra-warp halo via shuffle (no barrier, no smem) ----
        float vprev = __shfl_up_sync(fm, c[EPT - 1], 1);
        float vnext = __shfl_down_sync(fm, c[0], 1);
        if (lid == 0)  vprev = pl;
        if (lid == 31) vnext = pn;

        // ---- Phase 1: scores in-place + value-only chunk max ----
        float m0 = -CUDART_INF_F, m1 = -CUDART_INF_F,
              m2 = -CUDART_INF_F, m3 = -CUDART_INF_F;
        {
            float prev = vprev;
#pragma unroll
            for (int j = 0; j < EPT; j++) {
                const float v = c[j];
                const float r = (j == EPT - 1) ? vnext : c[j + 1];
                const float mx = fmaxf(prev, r);
                const float sc = (v >= mx) ? v : 0.0f;  // smax==v <=> v >= max(l,r)
                c[j] = sc;
                prev = v;
                switch (j & 3) {
                    case 0: m0 = fmaxf(m0, sc); break;
                    case 1: m1 = fmaxf(m1, sc); break;
                    case 2: m2 = fmaxf(m2, sc); break;
                    default: m3 = fmaxf(m3, sc); break;
                }
            }
        }
        const float myMax = fmaxf(fmaxf(m0, m1), fmaxf(m2, m3));

        // ---- Warp top-3 of thread-maxima (values only) ----
        float a0 = myMax, a1 = -CUDART_INF_F, a2 = -CUDART_INF_F;
#pragma unroll
        for (int off = 16; off; off >>= 1) {
            float b0 = __shfl_down_sync(fm, a0, off);
            float b1 = __shfl_down_sync(fm, a1, off);
            float b2 = __shfl_down_sync(fm, a2, off);
            if (lid + off >= 32) { b0 = b1 = b2 = -CUDART_INF_F; }
            merge3(a0, a1, a2, b0, b1, b2);
        }
        if (lid == 0) {
            s_wtop[wid][0] = a0; s_wtop[wid][1] = a1; s_wtop[wid][2] = a2;
        }
        __syncthreads();                                   // B1

        // ---- Every warp redundantly reduces the NWARP triples -> t2 ----
        float u0 = -CUDART_INF_F, u1 = -CUDART_INF_F, u2 = -CUDART_INF_F;
        if (lid < NWARP) {
            u0 = s_wtop[lid][0]; u1 = s_wtop[lid][1]; u2 = s_wtop[lid][2];
        }
#pragma unroll
        for (int off = 8; off; off >>= 1) {   // lanes >= NWARP hold -inf already
            float b0 = __shfl_down_sync(fm, u0, off);
            float b1 = __shfl_down_sync(fm, u1, off);
            float b2 = __shfl_down_sync(fm, u2, off);
            merge3(u0, u1, u2, b0, b1, b2);
        }
        const float t2 = __shfl_sync(fm, u2, 0);  // 3rd-largest thread max

        // ---- Phase 2: only threads whose chunk max reaches t2 scan ----
        const bool cand = (myMax >= t2);
        if (__any_sync(fm, cand)) {
            if (cand) {
#pragma unroll
                for (int j = 0; j < EPT; j++) {
                    if (c[j] >= t2) {
                        int pos = atomicAdd(&s_cnt, 1);
                        if (pos < CAP) { s_val[pos] = c[j]; s_idx[pos] = start + j; }
                    }
                }
            }
        }
        __syncthreads();                                   // B2

        // ---- Warp 0: exact top-3 with (value desc, index asc) tie-break ----
        if (wid == 0) {
            int n = s_cnt; if (n > CAP) n = CAP;
            if (lid == 0) s_cnt = 0;   // reset for next row; safe: next-iteration
                                       // atomics happen only after next B1, which
                                       // needs warp 0 to arrive (post-reset).
            float s0 = -CUDART_INF_F, s1 = -CUDART_INF_F, s2 = -CUDART_INF_F;
            int   i0 = 0x7fffffff,    i1 = 0x7fffffff,    i2 = 0x7fffffff;
            for (int k = lid; k < n; k += 32)
                ins3(s_val[k], s_idx[k], s0, i0, s1, i1, s2, i2);
#pragma unroll
            for (int off = 16; off; off >>= 1) {
                float b0 = __shfl_down_sync(fm, s0, off);
                float b1 = __shfl_down_sync(fm, s1, off);
                float b2 = __shfl_down_sync(fm, s2, off);
                int   c0 = __shfl_down_sync(fm, i0, off);
                int   c1 = __shfl_down_sync(fm, i1, off);
                int   c2 = __shfl_down_sync(fm, i2, off);
                if (lid + off >= 32) {
                    b0 = b1 = b2 = -CUDART_INF_F;
                    c0 = c1 = c2 = 0x7fffffff;
                }
                ins3(b0, c0, s0, i0, s1, i1, s2, i2);
                ins3(b1, c1, s0, i0, s1, i1, s2, i2);
                ins3(b2, c2, s0, i0, s1, i1, s2, i2);
            }

            if (lid == 0) {
                // Output layout (return order, all fp32):
                //   [0       , ROWS*3) : neighbor_score
                //   [ROWS*3  , ROWS*6) : topk_scores
                //   [ROWS*6  , ROWS*9) : topk_index (int values, exact in fp32)
                const int top = i0;
#pragma unroll
                for (int k = 0; k < 3; k++) {
                    int nb = top - 1 + k;
                    nb = nb < 0 ? 0 : (nb > W - 1 ? W - 1 : nb);
                    out[(size_t)row * 3 + k] = __ldg(xr + nb);
                }
                const float ts[3] = {s0, s1, s2};
                const int   ti[3] = {i0, i1, i2};
#pragma unroll
                for (int k = 0; k < 3; k++) {
                    out[(size_t)ROWS * 3 + (size_t)row * 3 + k] = ts[k];
                    out[(size_t)ROWS * 6 + (size_t)row * 3 + k] = (float)(ti[k] - NLAG);
                }
            }
        }
    }
}

extern "C" void kernel_launch(void* const* d_in, const int* in_sizes, int n_in,
                              void* d_out, int out_size) {
    const float* x = (const float*)d_in[0];
    float* out = (float*)d_out;
    (void)in_sizes; (void)n_in; (void)out_size;
    peaks_kernel<<<GRID, TPB>>>(x, out);
}

// round 5
// speedup vs baseline: 1.4302x; 1.4302x over previous
#include <cuda_runtime.h>
#include <math_constants.h>

#define W      8192
#define ROWS   4096      // 16 * 1 * 256
#define NLAG   4096      // W / 2
#define TPB    512
#define EPT    16        // elements per thread (TPB * EPT == W)
#define NWARP  (TPB / 32)
#define CAP    256       // candidate buffer capacity (expected ~3-8 used)

__device__ __forceinline__ bool better(float v, int i, float v2, int i2) {
    return (v > v2) || (v == v2 && i < i2);
}

__device__ __forceinline__ void ins3(float v, int i,
                                     float& s0, int& i0,
                                     float& s1, int& i1,
                                     float& s2, int& i2) {
    if (better(v, i, s0, i0)) {
        s2 = s1; i2 = i1;
        s1 = s0; i1 = i0;
        s0 = v;  i0 = i;
    } else if (better(v, i, s1, i1)) {
        s2 = s1; i2 = i1;
        s1 = v;  i1 = i;
    } else if (better(v, i, s2, i2)) {
        s2 = v;  i2 = i;
    }
}

// Merge sorted (desc) triple (b0,b1,b2) into (a0,a1,a2). Values only, FMNMX net.
__device__ __forceinline__ void merge3(float& a0, float& a1, float& a2,
                                       float b0, float b1, float b2) {
    float r0 = fmaxf(a0, b0);
    float x  = fminf(a0, b0);
    float y  = fmaxf(a1, b1);
    float z  = fminf(a1, b1);
    float r1 = fmaxf(x, y);
    float s  = fminf(x, y);
    float r2 = fmaxf(fmaxf(s, z), fmaxf(a2, b2));
    a0 = r0; a1 = r1; a2 = r2;
}

__global__ __launch_bounds__(TPB, 4)
void peaks_kernel(const float* __restrict__ x, float* __restrict__ out) {
    const int row = blockIdx.x;
    const float* __restrict__ xr = x + (size_t)row * W;
    const int t   = threadIdx.x;
    const int lid = t & 31;
    const int wid = t >> 5;
    const int start = t * EPT;
    const unsigned fm = 0xffffffffu;

    __shared__ float s_edgeL[TPB];   // each thread's c[0]      (raw)
    __shared__ float s_edgeR[TPB];   // each thread's c[EPT-1]  (raw)
    __shared__ float s_wmax[NWARP];
    __shared__ float s_t;
    __shared__ int   s_cnt;
    __shared__ float s_val[CAP];
    __shared__ int   s_idx[CAP];

    // ---- Load chunk (4x LDG.128, front-batched) ----
    float c[EPT];
    const float4* p = reinterpret_cast<const float4*>(xr + start);
#pragma unroll
    for (int q = 0; q < EPT / 4; q++) {
        float4 v = p[q];
        c[q * 4 + 0] = v.x;
        c[q * 4 + 1] = v.y;
        c[q * 4 + 2] = v.z;
        c[q * 4 + 3] = v.w;
    }

    // ---- Halo exchange through shared memory ----
    s_edgeL[t] = c[0];
    s_edgeR[t] = c[EPT - 1];
    if (t == 0) s_cnt = 0;
    __syncthreads();                                          // B1
    const float vprev = (t > 0)       ? s_edgeR[t - 1] : -CUDART_INF_F;
    const float vnext = (t < TPB - 1) ? s_edgeL[t + 1] : -CUDART_INF_F;

    // ---- Phase 1: predicated peak-max, 3 ops/element, raw c[] preserved ----
    float m0 = -CUDART_INF_F, m1 = -CUDART_INF_F,
          m2 = -CUDART_INF_F, m3 = -CUDART_INF_F;
    {
        float prev = vprev;
#pragma unroll
        for (int j = 0; j < EPT; j++) {
            const float v = c[j];
            const float r = (j == EPT - 1) ? vnext : c[j + 1];
            const float mx = fmaxf(prev, r);
            // local max (smax==v) <=> v >= max(l, r); accumulate peak value
            if (v >= mx) {
                switch (j & 3) {
                    case 0: m0 = fmaxf(m0, v); break;
                    case 1: m1 = fmaxf(m1, v); break;
                    case 2: m2 = fmaxf(m2, v); break;
                    default: m3 = fmaxf(m3, v); break;
                }
            }
            prev = v;
        }
    }
    const float myMax = fmaxf(fmaxf(m0, m1), fmaxf(m2, m3));

    // ---- Warp max of per-thread peak maxima (duplicate-tolerant, no masks) ----
    float wmax = myMax;
#pragma unroll
    for (int off = 16; off; off >>= 1)
        wmax = fmaxf(wmax, __shfl_down_sync(fm, wmax, off));
    if (lid == 0) s_wmax[wid] = wmax;
    __syncthreads();                                          // B2

    // ---- Warp 0: 3rd-largest of the 16 warp maxima -> threshold ----
    // Valid lower bound: the 3 warps with the largest maxima each contain one
    // element >= u2, so the row's 3rd-largest score >= u2.
    if (wid == 0) {
        float u0 = (lid < NWARP) ? s_wmax[lid] : -CUDART_INF_F;
        float u1 = -CUDART_INF_F, u2 = -CUDART_INF_F;
#pragma unroll
        for (int off = 8; off; off >>= 1) {   // lanes 16..23 hold -inf; off<=8 never wraps
            float b0 = __shfl_down_sync(fm, u0, off);
            float b1 = __shfl_down_sync(fm, u1, off);
            float b2 = __shfl_down_sync(fm, u2, off);
            merge3(u0, u1, u2, b0, b1, b2);
        }
        if (lid == 0) s_t = u2;
    }
    __syncthreads();                                          // B3

    // ---- Phase 2: candidate threads recompute scores and push (~3/block) ----
    const float thr = s_t;
    if (myMax >= thr) {
        float prev = vprev;
#pragma unroll
        for (int j = 0; j < EPT; j++) {
            const float v = c[j];
            const float r = (j == EPT - 1) ? vnext : c[j + 1];
            const float mx = fmaxf(prev, r);
            const float sc = (v >= mx) ? v : 0.0f;
            if (sc >= thr) {
                int pos = atomicAdd(&s_cnt, 1);
                if (pos < CAP) { s_val[pos] = sc; s_idx[pos] = start + j; }
            }
            prev = v;
        }
    }
    __syncthreads();                                          // B4

    // ---- Thread 0: exact top-3 over tiny candidate list, then outputs ----
    if (t == 0) {
        int n = s_cnt; if (n > CAP) n = CAP;
        float s0 = -CUDART_INF_F, s1 = -CUDART_INF_F, s2 = -CUDART_INF_F;
        int   i0 = 0x7fffffff,    i1 = 0x7fffffff,    i2 = 0x7fffffff;
        for (int k = 0; k < n; k++)
            ins3(s_val[k], s_idx[k], s0, i0, s1, i1, s2, i2);

        // Output layout (return order, all fp32):
        //   [0       , ROWS*3) : neighbor_score
        //   [ROWS*3  , ROWS*6) : topk_scores
        //   [ROWS*6  , ROWS*9) : topk_index (int values, exact in fp32)
        const int top = i0;
#pragma unroll
        for (int k = 0; k < 3; k++) {
            int nb = top - 1 + k;
            nb = nb < 0 ? 0 : (nb > W - 1 ? W - 1 : nb);
            out[(size_t)row * 3 + k] = __ldg(xr + nb);
        }
        const float ts[3] = {s0, s1, s2};
        const int   ti[3] = {i0, i1, i2};
#pragma unroll
        for (int k = 0; k < 3; k++) {
            out[(size_t)ROWS * 3 + (size_t)row * 3 + k] = ts[k];
            out[(size_t)ROWS * 6 + (size_t)row * 3 + k] = (float)(ti[k] - NLAG);
        }
    }
}

extern "C" void kernel_launch(void* const* d_in, const int* in_sizes, int n_in,
                              void* d_out, int out_size) {
    const float* x = (const float*)d_in[0];
    float* out = (float*)d_out;
    (void)in_sizes; (void)n_in; (void)out_size;
    peaks_kernel<<<ROWS, TPB>>>(x, out);
}